// round 13
// baseline (speedup 1.0000x reference)
#include <cuda_runtime.h>
#include <cuda_bf16.h>
#include <math.h>
#include <stdint.h>

#define S_ 8192
#define D_ 2048
#define H_ 2048
#define F_ 8192
#define NCHUNK 64
#define CHUNK_LEN 128   // S_ / NCHUNK

typedef unsigned int u32;
typedef unsigned long long u64;
typedef __nv_bfloat16 bf16;

// ---------------- scratch (static device globals; no allocation) ----------------
__device__ float g_xh  [(size_t)S_ * H_];
__device__ float g_apre[(size_t)S_ * H_];
__device__ float g_gpre[(size_t)S_ * H_];
__device__ float g_res [(size_t)S_ * D_];
__device__ float g_xn  [(size_t)S_ * D_];
__device__ float g_cA[(size_t)NCHUNK * H_];
__device__ float g_cB[(size_t)NCHUNK * H_];
__device__ float g_carry[(size_t)NCHUNK * H_];

// split (hi/lo bf16), tiled layout: tile t = (row>>7)*(K>>6) + (col>>6),
// 16384 bytes per tile, inner offset = swz((row&127)*128 + (col&63)*2)
__device__ bf16 g_xs_h [(size_t)S_ * D_];  __device__ bf16 g_xs_l [(size_t)S_ * D_];
__device__ bf16 g_hs_h [(size_t)S_ * H_];  __device__ bf16 g_hs_l [(size_t)S_ * H_];
__device__ bf16 g_xns_h[(size_t)S_ * D_];  __device__ bf16 g_xns_l[(size_t)S_ * D_];
__device__ bf16 g_ts_h [(size_t)S_ * F_];  __device__ bf16 g_ts_l [(size_t)S_ * F_];
__device__ bf16 g_win_h [(size_t)H_ * D_]; __device__ bf16 g_win_l [(size_t)H_ * D_];
__device__ bf16 g_wa_h  [(size_t)H_ * D_]; __device__ bf16 g_wa_l  [(size_t)H_ * D_];
__device__ bf16 g_wg_h  [(size_t)H_ * D_]; __device__ bf16 g_wg_l  [(size_t)H_ * D_];
__device__ bf16 g_wout_h[(size_t)D_ * H_]; __device__ bf16 g_wout_l[(size_t)D_ * H_];
__device__ bf16 g_w1_h  [(size_t)F_ * D_]; __device__ bf16 g_w1_l  [(size_t)F_ * D_];
__device__ bf16 g_w2_h  [(size_t)D_ * F_]; __device__ bf16 g_w2_l  [(size_t)D_ * F_];

// ---------------- scalar helpers ----------------
__device__ __forceinline__ float sigmoidf_(float x) { return 1.0f / (1.0f + expf(-x)); }
__device__ __forceinline__ float log_sigmoidf_(float x) {
    return (x >= 0.0f) ? -log1pf(expf(-x)) : (x - log1pf(expf(x)));
}
__device__ __forceinline__ float gelu_tanh_(float x) {
    float x3 = x * x * x;
    float t = tanhf(0.7978845608028654f * (x + 0.044715f * x3));
    return 0.5f * x * (1.0f + t);
}
__device__ __forceinline__ float block_reduce_sum_256(float v) {
    __shared__ float red[8];
    int lane = threadIdx.x & 31, w = threadIdx.x >> 5;
    #pragma unroll
    for (int o = 16; o; o >>= 1) v += __shfl_xor_sync(0xffffffffu, v, o);
    if (lane == 0) red[w] = v;
    __syncthreads();
    if (w == 0) {
        v = (lane < 8) ? red[lane] : 0.0f;
        #pragma unroll
        for (int o = 4; o; o >>= 1) v += __shfl_xor_sync(0xffffffffu, v, o);
        if (lane == 0) red[0] = v;
    }
    __syncthreads();
    return red[0];
}
__device__ __forceinline__ u32 swz_(u32 o) { return o ^ ((o >> 3) & 0x70); }

// ---------------- base-ISA PTX wrappers (sm_80+, valid on plain sm_103) --------
__device__ __forceinline__ u32 s2u(const void* p) {
    u32 a;
    asm("{ .reg .u64 t; cvta.to.shared.u64 t, %1; cvt.u32.u64 %0, t; }" : "=r"(a) : "l"(p));
    return a;
}
__device__ __forceinline__ void cpa16(u32 dst, const void* src) {
    asm volatile("cp.async.cg.shared.global [%0], [%1], 16;" :: "r"(dst), "l"(src) : "memory");
}
__device__ __forceinline__ void ldm4(u32* r, u32 addr) {
    asm volatile("ldmatrix.sync.aligned.m8n8.x4.shared.b16 {%0,%1,%2,%3}, [%4];"
                 : "=r"(r[0]), "=r"(r[1]), "=r"(r[2]), "=r"(r[3]) : "r"(addr));
}
__device__ __forceinline__ void mma16816(float* c, const u32* a, u32 b0, u32 b1) {
    asm volatile(
        "mma.sync.aligned.m16n8k16.row.col.f32.bf16.bf16.f32 "
        "{%0,%1,%2,%3}, {%4,%5,%6,%7}, {%8,%9}, {%0,%1,%2,%3};"
        : "+f"(c[0]), "+f"(c[1]), "+f"(c[2]), "+f"(c[3])
        : "r"(a[0]), "r"(a[1]), "r"(a[2]), "r"(a[3]), "r"(b0), "r"(b1));
}

// ---------------- split-bf16 GEMM on HMMA (mma.sync), 3-product ----------------
// C[m,n] = sum_k A[m,k]*W[n,k] + bias[n]
// CTA tile 128x128, BK=64. 3-product split: AhBh + AhBl + AlBh (ll term ~2^-18, dropped).
// Inputs pre-split + pre-swizzled 16KB tiles (128 rows x 128B, SW128).
#define STAGE 65536          // Ah16K | Al16K | Bh16K | Bl16K
#define GSMEM (2 * STAGE)

__global__ __launch_bounds__(256, 1)
void gemm_mma(const bf16* __restrict__ Ah, const bf16* __restrict__ Al,
              const bf16* __restrict__ Bh, const bf16* __restrict__ Bl,
              const float* __restrict__ bias, float* __restrict__ C,
              bf16* __restrict__ Ch, bf16* __restrict__ Cl,
              int N, int K, int fuse_gelu, int split_out)
{
    extern __shared__ char smem[];
    const u32 sb = s2u(smem);
    const int tid = threadIdx.x, wid = tid >> 5, lane = tid & 31;
    const int wm = wid >> 2, wn = wid & 3;     // warp grid 2(M) x 4(N)
    const int KB = K >> 6;
    const int rb = blockIdx.y, cb = blockIdx.x;
    const int g = lane >> 3, lr = lane & 7;    // ldmatrix address groups

    const char* gAh = (const char*)Ah + (size_t)rb * KB * 16384;
    const char* gAl = (const char*)Al + (size_t)rb * KB * 16384;
    const char* gBh = (const char*)Bh + (size_t)cb * KB * 16384;
    const char* gBl = (const char*)Bl + (size_t)cb * KB * 16384;

    float acc[4][4][4];
    #pragma unroll
    for (int i = 0; i < 4; i++)
        #pragma unroll
        for (int j = 0; j < 4; j++)
            #pragma unroll
            for (int e = 0; e < 4; e++) acc[i][j][e] = 0.0f;

    // per-lane ldmatrix address components (swz(r*128 + u*16) = r*128 + ((u^(r&7))<<4))
    u32 aRow[4], aXor[4], bRow[2], bXor[2];
    #pragma unroll
    for (int mt = 0; mt < 4; mt++) {
        int r = wm * 64 + mt * 16 + (g & 1) * 8 + lr;
        aRow[mt] = (u32)r << 7; aXor[mt] = (u32)(r & 7);
    }
    #pragma unroll
    for (int bt = 0; bt < 2; bt++) {
        int n = wn * 32 + bt * 16 + (g >> 1) * 8 + lr;
        bRow[bt] = (u32)n << 7; bXor[bt] = (u32)(n & 7);
    }

    // prologue: k-tile 0 -> stage 0
    {
        u32 d = sb;
        #pragma unroll
        for (int i = 0; i < 4; i++) {
            u32 off = (u32)(tid + i * 256) * 16;
            cpa16(d + off,         gAh + off);
            cpa16(d + 16384 + off, gAl + off);
            cpa16(d + 32768 + off, gBh + off);
            cpa16(d + 49152 + off, gBl + off);
        }
        asm volatile("cp.async.commit_group;" ::: "memory");
    }

    for (int kt = 0; kt < KB; kt++) {
        int s = kt & 1;
        if (kt + 1 < KB) {
            u32 d = sb + (u32)(s ^ 1) * STAGE;
            size_t ko = (size_t)(kt + 1) * 16384;
            #pragma unroll
            for (int i = 0; i < 4; i++) {
                u32 off = (u32)(tid + i * 256) * 16;
                cpa16(d + off,         gAh + ko + off);
                cpa16(d + 16384 + off, gAl + ko + off);
                cpa16(d + 32768 + off, gBh + ko + off);
                cpa16(d + 49152 + off, gBl + ko + off);
            }
            asm volatile("cp.async.commit_group;" ::: "memory");
            asm volatile("cp.async.wait_group 1;" ::: "memory");
        } else {
            asm volatile("cp.async.wait_group 0;" ::: "memory");
        }
        __syncthreads();

        const u32 aHi = sb + (u32)s * STAGE;
        const u32 aLo = aHi + 16384;
        const u32 bHi = aHi + 32768;
        const u32 bLo = aHi + 49152;

        #pragma unroll
        for (int ks = 0; ks < 4; ks++) {
            const u32 au = (u32)(ks * 2 + (g >> 1));
            const u32 bu = (u32)(ks * 2 + (g & 1));
            u32 AH[4][4], AL[4][4], BH[2][4], BL[2][4];
            #pragma unroll
            for (int mt = 0; mt < 4; mt++)
                ldm4(AH[mt], aHi + aRow[mt] + ((au ^ aXor[mt]) << 4));
            #pragma unroll
            for (int bt = 0; bt < 2; bt++)
                ldm4(BH[bt], bHi + bRow[bt] + ((bu ^ bXor[bt]) << 4));
            #pragma unroll
            for (int bt = 0; bt < 2; bt++)
                ldm4(BL[bt], bLo + bRow[bt] + ((bu ^ bXor[bt]) << 4));
            #pragma unroll
            for (int mt = 0; mt < 4; mt++)
                ldm4(AL[mt], aLo + aRow[mt] + ((au ^ aXor[mt]) << 4));

            // hh
            #pragma unroll
            for (int mt = 0; mt < 4; mt++)
                #pragma unroll
                for (int nt = 0; nt < 4; nt++) {
                    u32 b0 = BH[nt >> 1][(nt & 1) * 2], b1 = BH[nt >> 1][(nt & 1) * 2 + 1];
                    mma16816(acc[mt][nt], AH[mt], b0, b1);
                }
            // hl
            #pragma unroll
            for (int mt = 0; mt < 4; mt++)
                #pragma unroll
                for (int nt = 0; nt < 4; nt++) {
                    u32 b0 = BL[nt >> 1][(nt & 1) * 2], b1 = BL[nt >> 1][(nt & 1) * 2 + 1];
                    mma16816(acc[mt][nt], AH[mt], b0, b1);
                }
            // lh   (ll dropped: contributes ~2^-18 relative)
            #pragma unroll
            for (int mt = 0; mt < 4; mt++)
                #pragma unroll
                for (int nt = 0; nt < 4; nt++) {
                    u32 b0 = BH[nt >> 1][(nt & 1) * 2], b1 = BH[nt >> 1][(nt & 1) * 2 + 1];
                    mma16816(acc[mt][nt], AL[mt], b0, b1);
                }
        }
        __syncthreads();
    }

    // epilogue. c-frag: c0=(r,c) c1=(r,c+1) c2=(r+8,c) c3=(r+8,c+1); r=lane/4, c=(lane%4)*2
    const int r0 = rb * 128 + wm * 64 + (lane >> 2);
    const int c0 = cb * 128 + wn * 32 + (lane & 3) * 2;
    const int KBo = N >> 6;
    #pragma unroll
    for (int mt = 0; mt < 4; mt++) {
        #pragma unroll
        for (int nt = 0; nt < 4; nt++) {
            int r = r0 + mt * 16;
            int c = c0 + nt * 8;
            float b0 = bias[c], b1 = bias[c + 1];
            float v0 = acc[mt][nt][0] + b0, v1 = acc[mt][nt][1] + b1;
            float v2 = acc[mt][nt][2] + b0, v3 = acc[mt][nt][3] + b1;
            if (fuse_gelu) {
                v0 = gelu_tanh_(v0); v1 = gelu_tanh_(v1);
                v2 = gelu_tanh_(v2); v3 = gelu_tanh_(v3);
            }
            if (!split_out) {
                float2 f0 = { v0, v1 }, f1 = { v2, v3 };
                *(float2*)&C[(size_t)r * N + c]       = f0;
                *(float2*)&C[(size_t)(r + 8) * N + c] = f1;
            } else {
                #pragma unroll
                for (int half = 0; half < 2; half++) {
                    int rr = r + half * 8;
                    float x0 = half ? v2 : v0, x1 = half ? v3 : v1;
                    bf16 h0 = __float2bfloat16(x0), h1 = __float2bfloat16(x1);
                    bf16 l0 = __float2bfloat16(x0 - __bfloat162float(h0));
                    bf16 l1 = __float2bfloat16(x1 - __bfloat162float(h1));
                    size_t off = (size_t)((rr >> 7) * KBo + (c >> 6)) * 16384
                               + swz_(((u32)(rr & 127) << 7) + ((u32)(c & 63) << 1));
                    union { bf16 b[2]; u32 u; } H, L;
                    H.b[0] = h0; H.b[1] = h1; L.b[0] = l0; L.b[1] = l1;
                    *(u32*)((char*)Ch + off) = H.u;
                    *(u32*)((char*)Cl + off) = L.u;
                }
            }
        }
    }
}

// ---------------- split fp32 [R,K] -> hi/lo bf16 tiles ----------------
__global__ void split_mat(const float* __restrict__ src, bf16* __restrict__ hi,
                          bf16* __restrict__ lo, int R, int K)
{
    size_t i = (size_t)blockIdx.x * 256 + threadIdx.x;   // one 8-elem chunk per thread
    size_t n8 = (size_t)R * K >> 3;
    if (i >= n8) return;
    int K8 = K >> 3;
    int r = (int)(i / K8);
    int k = (int)(i % K8) << 3;
    const float4* s = (const float4*)(src + (size_t)r * K + k);
    float4 f0 = s[0], f1 = s[1];
    float v[8] = { f0.x, f0.y, f0.z, f0.w, f1.x, f1.y, f1.z, f1.w };
    union { bf16 b[8]; uint4 u; } Hh, Ll;
    #pragma unroll
    for (int j = 0; j < 8; j++) {
        bf16 h = __float2bfloat16(v[j]);
        Hh.b[j] = h;
        Ll.b[j] = __float2bfloat16(v[j] - __bfloat162float(h));
    }
    size_t off = (size_t)((r >> 7) * (K >> 6) + (k >> 6)) * 16384
               + swz_(((u32)(r & 127) << 7) + ((u32)(k & 63) << 1));
    *(uint4*)((char*)hi + off) = Hh.u;
    *(uint4*)((char*)lo + off) = Ll.u;
}

// ---------------- elementwise: (a, b) scan coefficients ----------------
__global__ void compute_ab(float* __restrict__ xh, float* __restrict__ ap,
                           const float* __restrict__ gp, const float* __restrict__ lam,
                           size_t n, int H)
{
    size_t i = (size_t)blockIdx.x * blockDim.x + threadIdx.x;
    if (i >= n) return;
    int h = (int)(i % (size_t)H);
    float r = sigmoidf_(ap[i]);
    float g = sigmoidf_(gp[i]);
    float ls = log_sigmoidf_(lam[h]);
    float la = 8.0f * r * ls;
    float a = expf(la);
    float omega = 1.0f - expf(2.0f * la);
    if (omega < 0.0f) omega = 0.0f;
    float b = sqrtf(omega) * (g * xh[i]);
    ap[i] = a;
    xh[i] = b;
}

// ---------------- blocked linear scan ----------------
__global__ void scan_chunk_reduce(const float* __restrict__ a, const float* __restrict__ b,
                                  float* __restrict__ cA, float* __restrict__ cB, int H)
{
    int h = blockIdx.x * blockDim.x + threadIdx.x;
    int c = blockIdx.y;
    size_t base = (size_t)c * CHUNK_LEN * H + h;
    float A = 1.0f, B = 0.0f;
    #pragma unroll 4
    for (int t = 0; t < CHUNK_LEN; t++) {
        float at = a[base + (size_t)t * H];
        float bt = b[base + (size_t)t * H];
        A = A * at;
        B = at * B + bt;
    }
    cA[(size_t)c * H + h] = A;
    cB[(size_t)c * H + h] = B;
}

__global__ void scan_carry(const float* __restrict__ cA, const float* __restrict__ cB,
                           float* __restrict__ carry, int H)
{
    int h = blockIdx.x * blockDim.x + threadIdx.x;
    float s = 0.0f;
    for (int c = 0; c < NCHUNK; c++) {
        carry[(size_t)c * H + h] = s;
        s = cA[(size_t)c * H + h] * s + cB[(size_t)c * H + h];
    }
}

// scan apply, writing h directly as split bf16 tiles (K = H)
__global__ void scan_apply_split(const float* __restrict__ a, const float* __restrict__ b,
                                 const float* __restrict__ carry,
                                 bf16* __restrict__ hi, bf16* __restrict__ lo, int H)
{
    int h = blockIdx.x * blockDim.x + threadIdx.x;   // column
    int c = blockIdx.y;                               // chunk (= row>>7, CHUNK_LEN=128)
    size_t base = (size_t)c * CHUNK_LEN * H + h;
    int KB = H >> 6;
    size_t tile0 = (size_t)(c * KB + (h >> 6)) * 16384;
    u32 cin = (u32)(h & 63) << 1;
    float s = carry[(size_t)c * H + h];
    #pragma unroll 4
    for (int t = 0; t < CHUNK_LEN; t++) {
        s = a[base + (size_t)t * H] * s + b[base + (size_t)t * H];
        bf16 hh = __float2bfloat16(s);
        bf16 ll = __float2bfloat16(s - __bfloat162float(hh));
        size_t off = tile0 + swz_(((u32)t << 7) + cin);
        *(bf16*)((char*)hi + off) = hh;
        *(bf16*)((char*)lo + off) = ll;
    }
}

// ------ fused: per-row gate prob + gated residual add + RMSNorm (+ split out) ------
__global__ void gate_norm_fused(const float* __restrict__ X, const float* __restrict__ R,
                                const float* __restrict__ aw, const float* __restrict__ ab,
                                const float* __restrict__ u,
                                const float* __restrict__ nw, const float* __restrict__ nb,
                                float* __restrict__ out, bf16* __restrict__ sh,
                                bf16* __restrict__ sl, int D)
{
    int s = blockIdx.x;
    const float* xr = X + (size_t)s * D;
    const float* rr = R + (size_t)s * D;

    // gate probability: sigmoid(res . aw + ab)
    float dot = 0.0f;
    float rv[8];
    #pragma unroll
    for (int i = 0; i < 8; i++) {
        int c = threadIdx.x + i * 256;
        float r = rr[c];
        rv[i] = r;
        dot += r * aw[c];
    }
    dot = block_reduce_sum_256(dot);
    bool gate = u[s] < sigmoidf_(dot + ab[0]);

    float vals[8];
    float ss = 0.0f;
    #pragma unroll
    for (int i = 0; i < 8; i++) {
        int c = threadIdx.x + i * 256;
        float v = xr[c] + (gate ? rv[i] : 0.0f);
        vals[i] = v;
        ss += v * v;
    }
    ss = block_reduce_sum_256(ss);
    float inv = rsqrtf(ss / (float)D + 1e-6f);
    int KB = D >> 6;
    #pragma unroll
    for (int i = 0; i < 8; i++) {
        int c = threadIdx.x + i * 256;
        float v = vals[i] * inv * nw[c] + nb[c];
        out[(size_t)s * D + c] = v;
        if (sh) {
            bf16 hh = __float2bfloat16(v);
            bf16 ll = __float2bfloat16(v - __bfloat162float(hh));
            size_t off = (size_t)((s >> 7) * KB + (c >> 6)) * 16384
                       + swz_(((u32)(s & 127) << 7) + ((u32)(c & 63) << 1));
            *(bf16*)((char*)sh + off) = hh;
            *(bf16*)((char*)sl + off) = ll;
        }
    }
}

// ---------------- launch ----------------
extern "C" void kernel_launch(void* const* d_in, const int* in_sizes, int n_in,
                              void* d_out, int out_size)
{
    const float* x      = (const float*)d_in[0];
    const float* W_in   = (const float*)d_in[1];
    const float* b_in   = (const float*)d_in[2];
    const float* W_a    = (const float*)d_in[3];
    const float* b_a    = (const float*)d_in[4];
    const float* W_g    = (const float*)d_in[5];
    const float* b_g    = (const float*)d_in[6];
    const float* lam    = (const float*)d_in[7];
    const float* W_out  = (const float*)d_in[8];
    const float* b_out  = (const float*)d_in[9];
    const float* ffn_w1 = (const float*)d_in[10];
    const float* ffn_b1 = (const float*)d_in[11];
    const float* ffn_w2 = (const float*)d_in[12];
    const float* ffn_b2 = (const float*)d_in[13];
    const float* act1_w = (const float*)d_in[14];
    const float* act1_b = (const float*)d_in[15];
    const float* act2_w = (const float*)d_in[16];
    const float* act2_b = (const float*)d_in[17];
    const float* n1w    = (const float*)d_in[18];
    const float* n1b    = (const float*)d_in[19];
    const float* n2w    = (const float*)d_in[20];
    const float* n2b    = (const float*)d_in[21];
    const float* u1     = (const float*)d_in[22];
    const float* u2     = (const float*)d_in[23];
    float* out = (float*)d_out;

    float *p_xh, *p_apre, *p_gpre, *p_res, *p_xn, *p_cA, *p_cB, *p_carry;
    cudaGetSymbolAddress((void**)&p_xh,    g_xh);
    cudaGetSymbolAddress((void**)&p_apre,  g_apre);
    cudaGetSymbolAddress((void**)&p_gpre,  g_gpre);
    cudaGetSymbolAddress((void**)&p_res,   g_res);
    cudaGetSymbolAddress((void**)&p_xn,    g_xn);
    cudaGetSymbolAddress((void**)&p_cA,    g_cA);
    cudaGetSymbolAddress((void**)&p_cB,    g_cB);
    cudaGetSymbolAddress((void**)&p_carry, g_carry);

    bf16 *xs_h, *xs_l, *hs_h, *hs_l, *xns_h, *xns_l, *ts_h, *ts_l;
    bf16 *win_h, *win_l, *wa_h, *wa_l, *wg_h, *wg_l, *wout_h, *wout_l, *w1_h, *w1_l, *w2_h, *w2_l;
    cudaGetSymbolAddress((void**)&xs_h,  g_xs_h);  cudaGetSymbolAddress((void**)&xs_l,  g_xs_l);
    cudaGetSymbolAddress((void**)&hs_h,  g_hs_h);  cudaGetSymbolAddress((void**)&hs_l,  g_hs_l);
    cudaGetSymbolAddress((void**)&xns_h, g_xns_h); cudaGetSymbolAddress((void**)&xns_l, g_xns_l);
    cudaGetSymbolAddress((void**)&ts_h,  g_ts_h);  cudaGetSymbolAddress((void**)&ts_l,  g_ts_l);
    cudaGetSymbolAddress((void**)&win_h, g_win_h); cudaGetSymbolAddress((void**)&win_l, g_win_l);
    cudaGetSymbolAddress((void**)&wa_h,  g_wa_h);  cudaGetSymbolAddress((void**)&wa_l,  g_wa_l);
    cudaGetSymbolAddress((void**)&wg_h,  g_wg_h);  cudaGetSymbolAddress((void**)&wg_l,  g_wg_l);
    cudaGetSymbolAddress((void**)&wout_h,g_wout_h);cudaGetSymbolAddress((void**)&wout_l,g_wout_l);
    cudaGetSymbolAddress((void**)&w1_h,  g_w1_h);  cudaGetSymbolAddress((void**)&w1_l,  g_w1_l);
    cudaGetSymbolAddress((void**)&w2_h,  g_w2_h);  cudaGetSymbolAddress((void**)&w2_l,  g_w2_l);

    cudaFuncSetAttribute(gemm_mma, cudaFuncAttributeMaxDynamicSharedMemorySize, GSMEM);

    dim3 blk(256);
    const unsigned B_DD = (unsigned)((size_t)H_ * D_ / 2048);
    const unsigned B_FD = (unsigned)((size_t)F_ * D_ / 2048);
    const unsigned B_SD = (unsigned)((size_t)S_ * D_ / 2048);

    // --- splits (weights + x) ---
    split_mat<<<B_DD, blk>>>(W_in,   win_h,  win_l,  H_, D_);
    split_mat<<<B_DD, blk>>>(W_a,    wa_h,   wa_l,   H_, D_);
    split_mat<<<B_DD, blk>>>(W_g,    wg_h,   wg_l,   H_, D_);
    split_mat<<<B_DD, blk>>>(W_out,  wout_h, wout_l, D_, H_);
    split_mat<<<B_FD, blk>>>(ffn_w1, w1_h,   w1_l,   F_, D_);
    split_mat<<<B_FD, blk>>>(ffn_w2, w2_h,   w2_l,   D_, F_);
    split_mat<<<B_SD, blk>>>(x,      xs_h,   xs_l,   S_, D_);

    dim3 gDH(H_ / 128, S_ / 128);   // (16, 64)
    dim3 gF (F_ / 128, S_ / 128);   // (64, 64)

    // --- RG-LRU branch ---
    gemm_mma<<<gDH, blk, GSMEM>>>(xs_h, xs_l, win_h, win_l, b_in, p_xh,   0, 0, H_, D_, 0, 0);
    gemm_mma<<<gDH, blk, GSMEM>>>(xs_h, xs_l, wa_h,  wa_l,  b_a,  p_apre, 0, 0, H_, D_, 0, 0);
    gemm_mma<<<gDH, blk, GSMEM>>>(xs_h, xs_l, wg_h,  wg_l,  b_g,  p_gpre, 0, 0, H_, D_, 0, 0);

    size_t nSH = (size_t)S_ * H_;
    compute_ab<<<(unsigned)((nSH + 255) / 256), blk>>>(p_xh, p_apre, p_gpre, lam, nSH, H_);

    dim3 gScan(H_ / 256, NCHUNK);
    scan_chunk_reduce<<<gScan, blk>>>(p_apre, p_xh, p_cA, p_cB, H_);
    scan_carry<<<H_ / 256, blk>>>(p_cA, p_cB, p_carry, H_);
    scan_apply_split<<<gScan, blk>>>(p_apre, p_xh, p_carry, hs_h, hs_l, H_);

    gemm_mma<<<gDH, blk, GSMEM>>>(hs_h, hs_l, wout_h, wout_l, b_out, p_res, 0, 0, D_, H_, 0, 0);

    gate_norm_fused<<<S_, blk>>>(x, p_res, act1_w, act1_b, u1, n1w, n1b, p_xn, xns_h, xns_l, D_);

    // --- FFN branch ---
    gemm_mma<<<gF,  blk, GSMEM>>>(xns_h, xns_l, w1_h, w1_l, ffn_b1, 0, ts_h, ts_l, F_, D_, 1, 1);
    gemm_mma<<<gDH, blk, GSMEM>>>(ts_h,  ts_l,  w2_h, w2_l, ffn_b2, p_res, 0, 0, D_, F_, 0, 0);

    gate_norm_fused<<<S_, blk>>>(p_xn, p_res, act2_w, act2_b, u2, n2w, n2b, out, 0, 0, D_);
}

// round 14
// speedup vs baseline: 1.5438x; 1.5438x over previous
#include <cuda_runtime.h>
#include <cuda_bf16.h>
#include <math.h>
#include <stdint.h>

#define S_ 8192
#define D_ 2048
#define H_ 2048
#define F_ 8192
#define NCHUNK 64
#define CHUNK_LEN 128   // S_ / NCHUNK

typedef unsigned int u32;
typedef unsigned long long u64;
typedef __nv_bfloat16 bf16;

// ---------------- scratch (static device globals; no allocation) ----------------
__device__ float g_xh  [(size_t)S_ * H_];
__device__ float g_apre[(size_t)S_ * H_];
__device__ float g_gpre[(size_t)S_ * H_];
__device__ float g_res [(size_t)S_ * D_];
__device__ float g_xn  [(size_t)S_ * D_];
__device__ float g_cA[(size_t)NCHUNK * H_];
__device__ float g_cB[(size_t)NCHUNK * H_];
__device__ float g_carry[(size_t)NCHUNK * H_];

// split (hi/lo bf16), tiled layout: tile t = (row>>7)*(K>>6) + (col>>6),
// 16384 bytes per tile, inner offset = swz((row&127)*128 + (col&63)*2)
__device__ bf16 g_xs_h [(size_t)S_ * D_];  __device__ bf16 g_xs_l [(size_t)S_ * D_];
__device__ bf16 g_hs_h [(size_t)S_ * H_];  __device__ bf16 g_hs_l [(size_t)S_ * H_];
__device__ bf16 g_xns_h[(size_t)S_ * D_];  __device__ bf16 g_xns_l[(size_t)S_ * D_];
__device__ bf16 g_ts_h [(size_t)S_ * F_];  __device__ bf16 g_ts_l [(size_t)S_ * F_];
__device__ bf16 g_win_h [(size_t)H_ * D_]; __device__ bf16 g_win_l [(size_t)H_ * D_];
__device__ bf16 g_wa_h  [(size_t)H_ * D_]; __device__ bf16 g_wa_l  [(size_t)H_ * D_];
__device__ bf16 g_wg_h  [(size_t)H_ * D_]; __device__ bf16 g_wg_l  [(size_t)H_ * D_];
__device__ bf16 g_wout_h[(size_t)D_ * H_]; __device__ bf16 g_wout_l[(size_t)D_ * H_];
__device__ bf16 g_w1_h  [(size_t)F_ * D_]; __device__ bf16 g_w1_l  [(size_t)F_ * D_];
__device__ bf16 g_w2_h  [(size_t)D_ * F_]; __device__ bf16 g_w2_l  [(size_t)D_ * F_];

// ---------------- scalar helpers ----------------
__device__ __forceinline__ float sigmoidf_(float x) { return 1.0f / (1.0f + expf(-x)); }
__device__ __forceinline__ float log_sigmoidf_(float x) {
    return (x >= 0.0f) ? -log1pf(expf(-x)) : (x - log1pf(expf(x)));
}
__device__ __forceinline__ float gelu_tanh_(float x) {
    float x3 = x * x * x;
    float t = tanhf(0.7978845608028654f * (x + 0.044715f * x3));
    return 0.5f * x * (1.0f + t);
}
__device__ __forceinline__ float block_reduce_sum_256(float v) {
    __shared__ float red[8];
    int lane = threadIdx.x & 31, w = threadIdx.x >> 5;
    #pragma unroll
    for (int o = 16; o; o >>= 1) v += __shfl_xor_sync(0xffffffffu, v, o);
    if (lane == 0) red[w] = v;
    __syncthreads();
    if (w == 0) {
        v = (lane < 8) ? red[lane] : 0.0f;
        #pragma unroll
        for (int o = 4; o; o >>= 1) v += __shfl_xor_sync(0xffffffffu, v, o);
        if (lane == 0) red[0] = v;
    }
    __syncthreads();
    return red[0];
}
__device__ __forceinline__ u32 swz_(u32 o) { return o ^ ((o >> 3) & 0x70); }

// ---------------- base-ISA PTX wrappers (sm_80+, valid on plain sm_103) --------
__device__ __forceinline__ u32 s2u(const void* p) {
    u32 a;
    asm("{ .reg .u64 t; cvta.to.shared.u64 t, %1; cvt.u32.u64 %0, t; }" : "=r"(a) : "l"(p));
    return a;
}
__device__ __forceinline__ void cpa16(u32 dst, const void* src) {
    asm volatile("cp.async.cg.shared.global [%0], [%1], 16;" :: "r"(dst), "l"(src) : "memory");
}
__device__ __forceinline__ void ldm4(u32* r, u32 addr) {
    asm volatile("ldmatrix.sync.aligned.m8n8.x4.shared.b16 {%0,%1,%2,%3}, [%4];"
                 : "=r"(r[0]), "=r"(r[1]), "=r"(r[2]), "=r"(r[3]) : "r"(addr));
}
__device__ __forceinline__ void mma16816(float* c, const u32* a, u32 b0, u32 b1) {
    asm volatile(
        "mma.sync.aligned.m16n8k16.row.col.f32.bf16.bf16.f32 "
        "{%0,%1,%2,%3}, {%4,%5,%6,%7}, {%8,%9}, {%0,%1,%2,%3};"
        : "+f"(c[0]), "+f"(c[1]), "+f"(c[2]), "+f"(c[3])
        : "r"(a[0]), "r"(a[1]), "r"(a[2]), "r"(a[3]), "r"(b0), "r"(b1));
}

// ---------------- split-bf16 GEMM on HMMA (mma.sync), 3-product ----------------
// C[m,n] = sum_k A[m,k]*W[n,k] + bias[n]
// CTA tile 128x128, BK=64. 3-product split: AhBh + AhBl + AlBh (ll ~2^-18, dropped).
// Inputs pre-split + pre-swizzled 16KB tiles (128 rows x 128B, SW128).
// 3-stage cp.async pipeline, one __syncthreads per k-tile.
#define STAGE 65536          // Ah16K | Al16K | Bh16K | Bl16K
#define NSTG 3
#define GSMEM (NSTG * STAGE)

__global__ __launch_bounds__(256, 1)
void gemm_mma(const bf16* __restrict__ Ah, const bf16* __restrict__ Al,
              const bf16* __restrict__ Bh, const bf16* __restrict__ Bl,
              const float* __restrict__ bias, float* __restrict__ C,
              bf16* __restrict__ Ch, bf16* __restrict__ Cl,
              int N, int K, int fuse_gelu, int split_out)
{
    extern __shared__ char smem[];
    const u32 sb = s2u(smem);
    const int tid = threadIdx.x, wid = tid >> 5, lane = tid & 31;
    const int wm = wid >> 2, wn = wid & 3;     // warp grid 2(M) x 4(N)
    const int KB = K >> 6;
    const int rb = blockIdx.y, cb = blockIdx.x;
    const int g = lane >> 3, lr = lane & 7;    // ldmatrix address groups

    const char* gAh = (const char*)Ah + (size_t)rb * KB * 16384;
    const char* gAl = (const char*)Al + (size_t)rb * KB * 16384;
    const char* gBh = (const char*)Bh + (size_t)cb * KB * 16384;
    const char* gBl = (const char*)Bl + (size_t)cb * KB * 16384;

    float acc[4][4][4];
    #pragma unroll
    for (int i = 0; i < 4; i++)
        #pragma unroll
        for (int j = 0; j < 4; j++)
            #pragma unroll
            for (int e = 0; e < 4; e++) acc[i][j][e] = 0.0f;

    // per-lane ldmatrix address components (swz(r*128 + u*16) = r*128 + ((u^(r&7))<<4))
    u32 aRow[4], aXor[4], bRow[2], bXor[2];
    #pragma unroll
    for (int mt = 0; mt < 4; mt++) {
        int r = wm * 64 + mt * 16 + (g & 1) * 8 + lr;
        aRow[mt] = (u32)r << 7; aXor[mt] = (u32)(r & 7);
    }
    #pragma unroll
    for (int bt = 0; bt < 2; bt++) {
        int n = wn * 32 + bt * 16 + (g >> 1) * 8 + lr;
        bRow[bt] = (u32)n << 7; bXor[bt] = (u32)(n & 7);
    }

    // prologue: stages 0 and 1 hold k-tiles 0 and 1
    #pragma unroll
    for (int p = 0; p < 2; p++) {
        u32 d = sb + (u32)p * STAGE;
        size_t ko = (size_t)p * 16384;
        #pragma unroll
        for (int i = 0; i < 4; i++) {
            u32 off = (u32)(tid + i * 256) * 16;
            cpa16(d + off,         gAh + ko + off);
            cpa16(d + 16384 + off, gAl + ko + off);
            cpa16(d + 32768 + off, gBh + ko + off);
            cpa16(d + 49152 + off, gBl + ko + off);
        }
        asm volatile("cp.async.commit_group;" ::: "memory");
    }

    int stage = 0;
    for (int kt = 0; kt < KB; kt++) {
        // wait until k-tile kt's data has landed
        if (kt + 1 < KB) asm volatile("cp.async.wait_group 1;" ::: "memory");
        else             asm volatile("cp.async.wait_group 0;" ::: "memory");
        __syncthreads();   // also guarantees everyone finished reading the stage we refill

        // prefetch k-tile kt+2 into the stage last read at iteration kt-1
        if (kt + 2 < KB) {
            int ns = stage + 2; if (ns >= NSTG) ns -= NSTG;
            u32 d = sb + (u32)ns * STAGE;
            size_t ko = (size_t)(kt + 2) * 16384;
            #pragma unroll
            for (int i = 0; i < 4; i++) {
                u32 off = (u32)(tid + i * 256) * 16;
                cpa16(d + off,         gAh + ko + off);
                cpa16(d + 16384 + off, gAl + ko + off);
                cpa16(d + 32768 + off, gBh + ko + off);
                cpa16(d + 49152 + off, gBl + ko + off);
            }
            asm volatile("cp.async.commit_group;" ::: "memory");
        }

        const u32 aHi = sb + (u32)stage * STAGE;
        const u32 aLo = aHi + 16384;
        const u32 bHi = aHi + 32768;
        const u32 bLo = aHi + 49152;

        #pragma unroll
        for (int ks = 0; ks < 4; ks++) {
            const u32 au = (u32)(ks * 2 + (g >> 1));
            const u32 bu = (u32)(ks * 2 + (g & 1));
            u32 AH[4][4], AL[4][4], BH[2][4], BL[2][4];
            #pragma unroll
            for (int mt = 0; mt < 4; mt++)
                ldm4(AH[mt], aHi + aRow[mt] + ((au ^ aXor[mt]) << 4));
            #pragma unroll
            for (int bt = 0; bt < 2; bt++)
                ldm4(BH[bt], bHi + bRow[bt] + ((bu ^ bXor[bt]) << 4));
            #pragma unroll
            for (int bt = 0; bt < 2; bt++)
                ldm4(BL[bt], bLo + bRow[bt] + ((bu ^ bXor[bt]) << 4));
            #pragma unroll
            for (int mt = 0; mt < 4; mt++)
                ldm4(AL[mt], aLo + aRow[mt] + ((au ^ aXor[mt]) << 4));

            // hh
            #pragma unroll
            for (int mt = 0; mt < 4; mt++)
                #pragma unroll
                for (int nt = 0; nt < 4; nt++) {
                    u32 b0 = BH[nt >> 1][(nt & 1) * 2], b1 = BH[nt >> 1][(nt & 1) * 2 + 1];
                    mma16816(acc[mt][nt], AH[mt], b0, b1);
                }
            // hl
            #pragma unroll
            for (int mt = 0; mt < 4; mt++)
                #pragma unroll
                for (int nt = 0; nt < 4; nt++) {
                    u32 b0 = BL[nt >> 1][(nt & 1) * 2], b1 = BL[nt >> 1][(nt & 1) * 2 + 1];
                    mma16816(acc[mt][nt], AH[mt], b0, b1);
                }
            // lh   (ll dropped: contributes ~2^-18 relative)
            #pragma unroll
            for (int mt = 0; mt < 4; mt++)
                #pragma unroll
                for (int nt = 0; nt < 4; nt++) {
                    u32 b0 = BH[nt >> 1][(nt & 1) * 2], b1 = BH[nt >> 1][(nt & 1) * 2 + 1];
                    mma16816(acc[mt][nt], AL[mt], b0, b1);
                }
        }
        if (++stage >= NSTG) stage = 0;
    }

    // epilogue. c-frag: c0=(r,c) c1=(r,c+1) c2=(r+8,c) c3=(r+8,c+1); r=lane/4, c=(lane%4)*2
    const int r0 = rb * 128 + wm * 64 + (lane >> 2);
    const int c0 = cb * 128 + wn * 32 + (lane & 3) * 2;
    const int KBo = N >> 6;
    #pragma unroll
    for (int mt = 0; mt < 4; mt++) {
        #pragma unroll
        for (int nt = 0; nt < 4; nt++) {
            int r = r0 + mt * 16;
            int c = c0 + nt * 8;
            float b0 = bias[c], b1 = bias[c + 1];
            float v0 = acc[mt][nt][0] + b0, v1 = acc[mt][nt][1] + b1;
            float v2 = acc[mt][nt][2] + b0, v3 = acc[mt][nt][3] + b1;
            if (fuse_gelu) {
                v0 = gelu_tanh_(v0); v1 = gelu_tanh_(v1);
                v2 = gelu_tanh_(v2); v3 = gelu_tanh_(v3);
            }
            if (!split_out) {
                float2 f0 = { v0, v1 }, f1 = { v2, v3 };
                *(float2*)&C[(size_t)r * N + c]       = f0;
                *(float2*)&C[(size_t)(r + 8) * N + c] = f1;
            } else {
                #pragma unroll
                for (int half = 0; half < 2; half++) {
                    int rr = r + half * 8;
                    float x0 = half ? v2 : v0, x1 = half ? v3 : v1;
                    bf16 h0 = __float2bfloat16(x0), h1 = __float2bfloat16(x1);
                    bf16 l0 = __float2bfloat16(x0 - __bfloat162float(h0));
                    bf16 l1 = __float2bfloat16(x1 - __bfloat162float(h1));
                    size_t off = (size_t)((rr >> 7) * KBo + (c >> 6)) * 16384
                               + swz_(((u32)(rr & 127) << 7) + ((u32)(c & 63) << 1));
                    union { bf16 b[2]; u32 u; } H, L;
                    H.b[0] = h0; H.b[1] = h1; L.b[0] = l0; L.b[1] = l1;
                    *(u32*)((char*)Ch + off) = H.u;
                    *(u32*)((char*)Cl + off) = L.u;
                }
            }
        }
    }
}

// ---------------- split fp32 [R,K] -> hi/lo bf16 tiles ----------------
__global__ void split_mat(const float* __restrict__ src, bf16* __restrict__ hi,
                          bf16* __restrict__ lo, int R, int K)
{
    size_t i = (size_t)blockIdx.x * 256 + threadIdx.x;   // one 8-elem chunk per thread
    size_t n8 = (size_t)R * K >> 3;
    if (i >= n8) return;
    int K8 = K >> 3;
    int r = (int)(i / K8);
    int k = (int)(i % K8) << 3;
    const float4* s = (const float4*)(src + (size_t)r * K + k);
    float4 f0 = s[0], f1 = s[1];
    float v[8] = { f0.x, f0.y, f0.z, f0.w, f1.x, f1.y, f1.z, f1.w };
    union { bf16 b[8]; uint4 u; } Hh, Ll;
    #pragma unroll
    for (int j = 0; j < 8; j++) {
        bf16 h = __float2bfloat16(v[j]);
        Hh.b[j] = h;
        Ll.b[j] = __float2bfloat16(v[j] - __bfloat162float(h));
    }
    size_t off = (size_t)((r >> 7) * (K >> 6) + (k >> 6)) * 16384
               + swz_(((u32)(r & 127) << 7) + ((u32)(k & 63) << 1));
    *(uint4*)((char*)hi + off) = Hh.u;
    *(uint4*)((char*)lo + off) = Ll.u;
}

// ---------------- elementwise: (a, b) scan coefficients ----------------
__global__ void compute_ab(float* __restrict__ xh, float* __restrict__ ap,
                           const float* __restrict__ gp, const float* __restrict__ lam,
                           size_t n, int H)
{
    size_t i = (size_t)blockIdx.x * blockDim.x + threadIdx.x;
    if (i >= n) return;
    int h = (int)(i % (size_t)H);
    float r = sigmoidf_(ap[i]);
    float g = sigmoidf_(gp[i]);
    float ls = log_sigmoidf_(lam[h]);
    float la = 8.0f * r * ls;
    float a = expf(la);
    float omega = 1.0f - expf(2.0f * la);
    if (omega < 0.0f) omega = 0.0f;
    float b = sqrtf(omega) * (g * xh[i]);
    ap[i] = a;
    xh[i] = b;
}

// ---------------- blocked linear scan ----------------
__global__ void scan_chunk_reduce(const float* __restrict__ a, const float* __restrict__ b,
                                  float* __restrict__ cA, float* __restrict__ cB, int H)
{
    int h = blockIdx.x * blockDim.x + threadIdx.x;
    int c = blockIdx.y;
    size_t base = (size_t)c * CHUNK_LEN * H + h;
    float A = 1.0f, B = 0.0f;
    #pragma unroll 4
    for (int t = 0; t < CHUNK_LEN; t++) {
        float at = a[base + (size_t)t * H];
        float bt = b[base + (size_t)t * H];
        A = A * at;
        B = at * B + bt;
    }
    cA[(size_t)c * H + h] = A;
    cB[(size_t)c * H + h] = B;
}

__global__ void scan_carry(const float* __restrict__ cA, const float* __restrict__ cB,
                           float* __restrict__ carry, int H)
{
    int h = blockIdx.x * blockDim.x + threadIdx.x;
    float s = 0.0f;
    for (int c = 0; c < NCHUNK; c++) {
        carry[(size_t)c * H + h] = s;
        s = cA[(size_t)c * H + h] * s + cB[(size_t)c * H + h];
    }
}

// scan apply, writing h directly as split bf16 tiles (K = H)
__global__ void scan_apply_split(const float* __restrict__ a, const float* __restrict__ b,
                                 const float* __restrict__ carry,
                                 bf16* __restrict__ hi, bf16* __restrict__ lo, int H)
{
    int h = blockIdx.x * blockDim.x + threadIdx.x;   // column
    int c = blockIdx.y;                               // chunk (= row>>7, CHUNK_LEN=128)
    size_t base = (size_t)c * CHUNK_LEN * H + h;
    int KB = H >> 6;
    size_t tile0 = (size_t)(c * KB + (h >> 6)) * 16384;
    u32 cin = (u32)(h & 63) << 1;
    float s = carry[(size_t)c * H + h];
    #pragma unroll 4
    for (int t = 0; t < CHUNK_LEN; t++) {
        s = a[base + (size_t)t * H] * s + b[base + (size_t)t * H];
        bf16 hh = __float2bfloat16(s);
        bf16 ll = __float2bfloat16(s - __bfloat162float(hh));
        size_t off = tile0 + swz_(((u32)t << 7) + cin);
        *(bf16*)((char*)hi + off) = hh;
        *(bf16*)((char*)lo + off) = ll;
    }
}

// ------ fused: per-row gate prob + gated residual add + RMSNorm (+ split out) ------
__global__ void gate_norm_fused(const float* __restrict__ X, const float* __restrict__ R,
                                const float* __restrict__ aw, const float* __restrict__ ab,
                                const float* __restrict__ u,
                                const float* __restrict__ nw, const float* __restrict__ nb,
                                float* __restrict__ out, bf16* __restrict__ sh,
                                bf16* __restrict__ sl, int D)
{
    int s = blockIdx.x;
    const float* xr = X + (size_t)s * D;
    const float* rr = R + (size_t)s * D;

    // gate probability: sigmoid(res . aw + ab)
    float dot = 0.0f;
    float rv[8];
    #pragma unroll
    for (int i = 0; i < 8; i++) {
        int c = threadIdx.x + i * 256;
        float r = rr[c];
        rv[i] = r;
        dot += r * aw[c];
    }
    dot = block_reduce_sum_256(dot);
    bool gate = u[s] < sigmoidf_(dot + ab[0]);

    float vals[8];
    float ss = 0.0f;
    #pragma unroll
    for (int i = 0; i < 8; i++) {
        int c = threadIdx.x + i * 256;
        float v = xr[c] + (gate ? rv[i] : 0.0f);
        vals[i] = v;
        ss += v * v;
    }
    ss = block_reduce_sum_256(ss);
    float inv = rsqrtf(ss / (float)D + 1e-6f);
    int KB = D >> 6;
    #pragma unroll
    for (int i = 0; i < 8; i++) {
        int c = threadIdx.x + i * 256;
        float v = vals[i] * inv * nw[c] + nb[c];
        out[(size_t)s * D + c] = v;
        if (sh) {
            bf16 hh = __float2bfloat16(v);
            bf16 ll = __float2bfloat16(v - __bfloat162float(hh));
            size_t off = (size_t)((s >> 7) * KB + (c >> 6)) * 16384
                       + swz_(((u32)(s & 127) << 7) + ((u32)(c & 63) << 1));
            *(bf16*)((char*)sh + off) = hh;
            *(bf16*)((char*)sl + off) = ll;
        }
    }
}

// ---------------- launch ----------------
extern "C" void kernel_launch(void* const* d_in, const int* in_sizes, int n_in,
                              void* d_out, int out_size)
{
    const float* x      = (const float*)d_in[0];
    const float* W_in   = (const float*)d_in[1];
    const float* b_in   = (const float*)d_in[2];
    const float* W_a    = (const float*)d_in[3];
    const float* b_a    = (const float*)d_in[4];
    const float* W_g    = (const float*)d_in[5];
    const float* b_g    = (const float*)d_in[6];
    const float* lam    = (const float*)d_in[7];
    const float* W_out  = (const float*)d_in[8];
    const float* b_out  = (const float*)d_in[9];
    const float* ffn_w1 = (const float*)d_in[10];
    const float* ffn_b1 = (const float*)d_in[11];
    const float* ffn_w2 = (const float*)d_in[12];
    const float* ffn_b2 = (const float*)d_in[13];
    const float* act1_w = (const float*)d_in[14];
    const float* act1_b = (const float*)d_in[15];
    const float* act2_w = (const float*)d_in[16];
    const float* act2_b = (const float*)d_in[17];
    const float* n1w    = (const float*)d_in[18];
    const float* n1b    = (const float*)d_in[19];
    const float* n2w    = (const float*)d_in[20];
    const float* n2b    = (const float*)d_in[21];
    const float* u1     = (const float*)d_in[22];
    const float* u2     = (const float*)d_in[23];
    float* out = (float*)d_out;

    float *p_xh, *p_apre, *p_gpre, *p_res, *p_xn, *p_cA, *p_cB, *p_carry;
    cudaGetSymbolAddress((void**)&p_xh,    g_xh);
    cudaGetSymbolAddress((void**)&p_apre,  g_apre);
    cudaGetSymbolAddress((void**)&p_gpre,  g_gpre);
    cudaGetSymbolAddress((void**)&p_res,   g_res);
    cudaGetSymbolAddress((void**)&p_xn,    g_xn);
    cudaGetSymbolAddress((void**)&p_cA,    g_cA);
    cudaGetSymbolAddress((void**)&p_cB,    g_cB);
    cudaGetSymbolAddress((void**)&p_carry, g_carry);

    bf16 *xs_h, *xs_l, *hs_h, *hs_l, *xns_h, *xns_l, *ts_h, *ts_l;
    bf16 *win_h, *win_l, *wa_h, *wa_l, *wg_h, *wg_l, *wout_h, *wout_l, *w1_h, *w1_l, *w2_h, *w2_l;
    cudaGetSymbolAddress((void**)&xs_h,  g_xs_h);  cudaGetSymbolAddress((void**)&xs_l,  g_xs_l);
    cudaGetSymbolAddress((void**)&hs_h,  g_hs_h);  cudaGetSymbolAddress((void**)&hs_l,  g_hs_l);
    cudaGetSymbolAddress((void**)&xns_h, g_xns_h); cudaGetSymbolAddress((void**)&xns_l, g_xns_l);
    cudaGetSymbolAddress((void**)&ts_h,  g_ts_h);  cudaGetSymbolAddress((void**)&ts_l,  g_ts_l);
    cudaGetSymbolAddress((void**)&win_h, g_win_h); cudaGetSymbolAddress((void**)&win_l, g_win_l);
    cudaGetSymbolAddress((void**)&wa_h,  g_wa_h);  cudaGetSymbolAddress((void**)&wa_l,  g_wa_l);
    cudaGetSymbolAddress((void**)&wg_h,  g_wg_h);  cudaGetSymbolAddress((void**)&wg_l,  g_wg_l);
    cudaGetSymbolAddress((void**)&wout_h,g_wout_h);cudaGetSymbolAddress((void**)&wout_l,g_wout_l);
    cudaGetSymbolAddress((void**)&w1_h,  g_w1_h);  cudaGetSymbolAddress((void**)&w1_l,  g_w1_l);
    cudaGetSymbolAddress((void**)&w2_h,  g_w2_h);  cudaGetSymbolAddress((void**)&w2_l,  g_w2_l);

    cudaFuncSetAttribute(gemm_mma, cudaFuncAttributeMaxDynamicSharedMemorySize, GSMEM);

    dim3 blk(256);
    const unsigned B_DD = (unsigned)((size_t)H_ * D_ / 2048);
    const unsigned B_FD = (unsigned)((size_t)F_ * D_ / 2048);
    const unsigned B_SD = (unsigned)((size_t)S_ * D_ / 2048);

    // --- splits (weights + x) ---
    split_mat<<<B_DD, blk>>>(W_in,   win_h,  win_l,  H_, D_);
    split_mat<<<B_DD, blk>>>(W_a,    wa_h,   wa_l,   H_, D_);
    split_mat<<<B_DD, blk>>>(W_g,    wg_h,   wg_l,   H_, D_);
    split_mat<<<B_DD, blk>>>(W_out,  wout_h, wout_l, D_, H_);
    split_mat<<<B_FD, blk>>>(ffn_w1, w1_h,   w1_l,   F_, D_);
    split_mat<<<B_FD, blk>>>(ffn_w2, w2_h,   w2_l,   D_, F_);
    split_mat<<<B_SD, blk>>>(x,      xs_h,   xs_l,   S_, D_);

    dim3 gDH(H_ / 128, S_ / 128);   // (16, 64)
    dim3 gF (F_ / 128, S_ / 128);   // (64, 64)

    // --- RG-LRU branch ---
    gemm_mma<<<gDH, blk, GSMEM>>>(xs_h, xs_l, win_h, win_l, b_in, p_xh,   0, 0, H_, D_, 0, 0);
    gemm_mma<<<gDH, blk, GSMEM>>>(xs_h, xs_l, wa_h,  wa_l,  b_a,  p_apre, 0, 0, H_, D_, 0, 0);
    gemm_mma<<<gDH, blk, GSMEM>>>(xs_h, xs_l, wg_h,  wg_l,  b_g,  p_gpre, 0, 0, H_, D_, 0, 0);

    size_t nSH = (size_t)S_ * H_;
    compute_ab<<<(unsigned)((nSH + 255) / 256), blk>>>(p_xh, p_apre, p_gpre, lam, nSH, H_);

    dim3 gScan(H_ / 256, NCHUNK);
    scan_chunk_reduce<<<gScan, blk>>>(p_apre, p_xh, p_cA, p_cB, H_);
    scan_carry<<<H_ / 256, blk>>>(p_cA, p_cB, p_carry, H_);
    scan_apply_split<<<gScan, blk>>>(p_apre, p_xh, p_carry, hs_h, hs_l, H_);

    gemm_mma<<<gDH, blk, GSMEM>>>(hs_h, hs_l, wout_h, wout_l, b_out, p_res, 0, 0, D_, H_, 0, 0);

    gate_norm_fused<<<S_, blk>>>(x, p_res, act1_w, act1_b, u1, n1w, n1b, p_xn, xns_h, xns_l, D_);

    // --- FFN branch ---
    gemm_mma<<<gF,  blk, GSMEM>>>(xns_h, xns_l, w1_h, w1_l, ffn_b1, 0, ts_h, ts_l, F_, D_, 1, 1);
    gemm_mma<<<gDH, blk, GSMEM>>>(ts_h,  ts_l,  w2_h, w2_l, ffn_b2, p_res, 0, 0, D_, F_, 0, 0);

    gate_norm_fused<<<S_, blk>>>(p_xn, p_res, act2_w, act2_b, u2, n2w, n2b, out, 0, 0, D_);
}